// round 3
// baseline (speedup 1.0000x reference)
#include <cuda_runtime.h>
#include <math.h>

// Problem constants
#define BB 16
#define SS 600
#define EE 300
#define HH 512
#define NCC 2
#define DD 180000          // S*E
#define TT 3
#define KSPLIT 375
#define KC 480             // KSPLIT*KC = DD, KC % 32 == 0

#define N0_ELEMS (BB*DD)        // 2,880,000
#define N1_ELEMS (BB*HH)        // 8,192
#define N2_ELEMS (BB*NCC)       // 32
#define SC_ELEMS (BB*SS*SS)     // 5,760,000

// -------- device scratch (no allocation allowed) --------
__device__ __align__(16) float d_Wx[N0_ELEMS];
__device__ __align__(16) float d_g0[N0_ELEMS];
__device__ __align__(16) float d_scores[SC_ELEMS];
__device__ __align__(16) float d_pbuf[KSPLIT * N1_ELEMS];
__device__ __align__(16) float d_n0[N0_ELEMS];
__device__ __align__(16) float d_n1[N1_ELEMS];
__device__ __align__(16) float d_n2[N2_ELEMS];
__device__ __align__(16) float d_g2[N2_ELEMS];

// ============================================================
// Generic batched tiled GEMM, fp32.
// C[z] = alpha * A[z] * op(B[z])
//   NT=true : B stored [N,K]  (C[m,n] = sum_k A[m,k]*B[n,k])
//   NT=false: B stored [K,N]  (C[m,n] = sum_k A[m,k]*B[k,n])
// BM=BN=128, BK=8, 256 threads, 8x8 microtile.
// ============================================================
template<bool NT>
__global__ __launch_bounds__(256, 2)
void gemm128(const float* __restrict__ A, const float* __restrict__ Bm,
             float* __restrict__ C, int M, int N, int K,
             int lda, int ldb, int ldc,
             long sA, long sB, long sC, float alpha)
{
    __shared__ float As[8][128];
    __shared__ float Bs[8][128];

    const float* Ab = A  + (long)blockIdx.z * sA;
    const float* Bb = Bm + (long)blockIdx.z * sB;
    float*       Cb = C  + (long)blockIdx.z * sC;

    const int m0 = blockIdx.y * 128;
    const int n0 = blockIdx.x * 128;
    const int tid = threadIdx.x;
    const int ty = tid >> 4;      // 0..15
    const int tx = tid & 15;      // 0..15

    float acc[8][8];
#pragma unroll
    for (int i = 0; i < 8; i++)
#pragma unroll
        for (int j = 0; j < 8; j++) acc[i][j] = 0.f;

    const float4 zero4 = make_float4(0.f, 0.f, 0.f, 0.f);

    for (int k0 = 0; k0 < K; k0 += 8) {
        // ---- load A tile (128 x 8), transposed into As[k][m] ----
        {
            int row = tid >> 1, q = tid & 1;
            int m = m0 + row;
            int kx = k0 + q * 4;
            float4 v = (m < M && kx < K)
                ? *(const float4*)(Ab + (long)m * lda + kx) : zero4;
            As[q*4+0][row] = v.x;
            As[q*4+1][row] = v.y;
            As[q*4+2][row] = v.z;
            As[q*4+3][row] = v.w;
        }
        // ---- load B tile ----
        if (NT) {
            int row = tid >> 1, q = tid & 1;
            int n = n0 + row;
            int kx = k0 + q * 4;
            float4 v = (n < N && kx < K)
                ? *(const float4*)(Bb + (long)n * ldb + kx) : zero4;
            Bs[q*4+0][row] = v.x;
            Bs[q*4+1][row] = v.y;
            Bs[q*4+2][row] = v.z;
            Bs[q*4+3][row] = v.w;
        } else {
            int kr = tid >> 5, q = tid & 31;
            int kx = k0 + kr;
            int n = n0 + q * 4;
            float4 v = (kx < K && n < N)
                ? *(const float4*)(Bb + (long)kx * ldb + n) : zero4;
            *(float4*)&Bs[kr][q * 4] = v;
        }
        __syncthreads();

        // ---- compute ----
#pragma unroll
        for (int kk = 0; kk < 8; kk++) {
            float a[8], b[8];
            *(float4*)&a[0] = *(const float4*)&As[kk][ty * 8];
            *(float4*)&a[4] = *(const float4*)&As[kk][ty * 8 + 4];
            *(float4*)&b[0] = *(const float4*)&Bs[kk][tx * 8];
            *(float4*)&b[4] = *(const float4*)&Bs[kk][tx * 8 + 4];
#pragma unroll
            for (int i = 0; i < 8; i++)
#pragma unroll
                for (int j = 0; j < 8; j++)
                    acc[i][j] += a[i] * b[j];
        }
        __syncthreads();
    }

    // ---- store ----
#pragma unroll
    for (int i = 0; i < 8; i++) {
        int m = m0 + ty * 8 + i;
        if (m >= M) break;
#pragma unroll
        for (int j = 0; j < 8; j++) {
            int n = n0 + tx * 8 + j;
            if (n < N) Cb[(long)m * ldc + n] = alpha * acc[i][j];
        }
    }
}

// ============================================================
// g0[b,d] = Wx[b,d] + sum_h n1[b,h] * W1[h,d]
// 128 threads, each handles 2 consecutive d, 16 batch accumulators.
// ============================================================
__global__ __launch_bounds__(128)
void g0_kernel(const float* __restrict__ W1, const float* __restrict__ Wx,
               const float* __restrict__ n1, float* __restrict__ g0)
{
    __shared__ float sn1[HH * BB];   // [h][b], 32 KB
    const int tid = threadIdx.x;
    for (int i = tid; i < BB * HH; i += 128) {
        int b = i >> 9, h = i & 511;
        sn1[h * BB + b] = n1[i];
    }
    __syncthreads();

    long d0 = (long)blockIdx.x * 256 + tid * 2;
    if (d0 >= DD) return;

    float acc0[BB], acc1[BB];
#pragma unroll
    for (int b = 0; b < BB; b++) {
        acc0[b] = Wx[(long)b * DD + d0];
        acc1[b] = Wx[(long)b * DD + d0 + 1];
    }
    const float* wp = W1 + d0;
    for (int h = 0; h < HH; h++) {
        float2 w = *(const float2*)wp; wp += DD;
        const float* s = &sn1[h * BB];
#pragma unroll
        for (int b = 0; b < BB; b++) {
            float nv = s[b];
            acc0[b] += nv * w.x;
            acc1[b] += nv * w.y;
        }
    }
#pragma unroll
    for (int b = 0; b < BB; b++) {
        g0[(long)b * DD + d0]     = acc0[b];
        g0[(long)b * DD + d0 + 1] = acc1[b];
    }
}

// ============================================================
// g1 split-K partial: pbuf[blk][b][h] = sum_{d in chunk} n0[b,d]*W1[h,d]
// grid = KSPLIT blocks, 256 threads; each thread owns 2 h x 16 b.
// dynamic smem: sn0[16*KC] + sW1[512*33]
// ============================================================
extern __shared__ float g1_smem[];
__global__ __launch_bounds__(256)
void g1_partial(const float* __restrict__ W1, const float* __restrict__ n0,
                float* __restrict__ pbuf)
{
    float* sn0 = g1_smem;               // 16*KC
    float* sW1 = g1_smem + BB * KC;     // 512*33

    const int tid = threadIdx.x;
    const long kb = (long)blockIdx.x * KC;

    for (int i = tid; i < BB * KC; i += 256) {
        int b = i / KC, k = i - b * KC;
        sn0[i] = n0[(long)b * DD + kb + k];
    }

    float acc0[BB], acc1[BB];
#pragma unroll
    for (int b = 0; b < BB; b++) { acc0[b] = 0.f; acc1[b] = 0.f; }

    for (int sub = 0; sub < KC / 32; sub++) {
        __syncthreads();
        // stage W1[0:512][kb+sub*32 : +32] into sW1 (padded rows of 33)
#pragma unroll
        for (int i = 0; i < 16; i++) {
            int idx = i * 256 + tid;
            int row = idx >> 3, q = idx & 7;
            float4 v = *(const float4*)(W1 + (long)row * DD + kb + sub * 32 + q * 4);
            float* s = &sW1[row * 33 + q * 4];
            s[0] = v.x; s[1] = v.y; s[2] = v.z; s[3] = v.w;
        }
        __syncthreads();

#pragma unroll 4
        for (int kk = 0; kk < 32; kk++) {
            float w0 = sW1[tid * 33 + kk];
            float w1 = sW1[(tid + 256) * 33 + kk];
            const float* s = &sn0[sub * 32 + kk];
#pragma unroll
            for (int b = 0; b < BB; b++) {
                float nv = s[b * KC];
                acc0[b] += w0 * nv;
                acc1[b] += w1 * nv;
            }
        }
    }

    long base = (long)blockIdx.x * N1_ELEMS;
#pragma unroll
    for (int b = 0; b < BB; b++) {
        pbuf[base + b * HH + tid]       = acc0[b];
        pbuf[base + b * HH + tid + 256] = acc1[b];
    }
}

// g1 reduce + bias + n2@W2 + tanh -> n1
__global__ void g1_reduce(const float* __restrict__ pbuf, const float* __restrict__ b1,
                          const float* __restrict__ n2, const float* __restrict__ W2,
                          float* __restrict__ n1)
{
    int idx = blockIdx.x * blockDim.x + threadIdx.x;   // 8192
    int b = idx >> 9, h = idx & 511;
    float s = b1[h] + n2[b * 2] * W2[h] + n2[b * 2 + 1] * W2[HH + h];
    for (int k = 0; k < KSPLIT; k++)
        s += pbuf[(long)k * N1_ELEMS + idx];
    n1[idx] = tanhf(s);
}

// g2[b,c] = b2[c] + sum_h n1[b,h]*W2[c,h]
__global__ void g2_kernel(const float* __restrict__ n1, const float* __restrict__ W2,
                          const float* __restrict__ b2, float* __restrict__ g2)
{
    int t = threadIdx.x;
    if (t < 32) {
        int b = t >> 1, c = t & 1;
        float s = 0.f;
        for (int h = 0; h < HH; h++)
            s += n1[b * HH + h] * W2[c * HH + h];
        g2[t] = b2[c] + s;
    }
}

__global__ void n2_tanh(const float* __restrict__ g2, float* __restrict__ n2)
{
    int t = threadIdx.x;
    if (t < 32) n2[t] = tanhf(g2[t]);
}

// step-0 closed form: n1 = tanh(b1), n2 = tanh(b2)
__global__ void init_n12(const float* __restrict__ b1, const float* __restrict__ b2,
                         float* __restrict__ n1, float* __restrict__ n2)
{
    int idx = blockIdx.x * blockDim.x + threadIdx.x;
    if (idx < N1_ELEMS) n1[idx] = tanhf(b1[idx & 511]);
    else if (idx < N1_ELEMS + N2_ELEMS) {
        int r = idx - N1_ELEMS;
        n2[r] = tanhf(b2[r & 1]);
    }
}

// row softmax over 16*600 rows of length 600; one warp per row
__global__ void softmax_rows(float* __restrict__ S)
{
    int gwarp = (blockIdx.x * blockDim.x + threadIdx.x) >> 5;
    int lane = threadIdx.x & 31;
    if (gwarp >= BB * SS) return;
    float* row = S + (long)gwarp * SS;

    float v[19];
    float mx = -INFINITY;
#pragma unroll
    for (int i = 0; i < 19; i++) {
        int c = lane + i * 32;
        v[i] = (c < SS) ? row[c] : -INFINITY;
        mx = fmaxf(mx, v[i]);
    }
#pragma unroll
    for (int o = 16; o; o >>= 1) mx = fmaxf(mx, __shfl_xor_sync(0xffffffffu, mx, o));

    float sum = 0.f;
#pragma unroll
    for (int i = 0; i < 19; i++) {
        v[i] = expf(v[i] - mx);         // exp(-inf)=0 handles tail lanes
        sum += v[i];
    }
#pragma unroll
    for (int o = 16; o; o >>= 1) sum += __shfl_xor_sync(0xffffffffu, sum, o);
    float inv = 1.f / sum;
#pragma unroll
    for (int i = 0; i < 19; i++) {
        int c = lane + i * 32;
        if (c < SS) row[c] = v[i] * inv;
    }
}

// concat (n0, n1, n2) into d_out
__global__ void final_copy(const float* __restrict__ n0, const float* __restrict__ n1,
                           const float* __restrict__ n2, float* __restrict__ out)
{
    int idx = blockIdx.x * blockDim.x + threadIdx.x;
    if (idx < N0_ELEMS) out[idx] = n0[idx];
    else if (idx < N0_ELEMS + N1_ELEMS) out[idx] = n1[idx - N0_ELEMS];
    else if (idx < N0_ELEMS + N1_ELEMS + N2_ELEMS) out[idx] = n2[idx - N0_ELEMS - N1_ELEMS];
}

// ============================================================
extern "C" void kernel_launch(void* const* d_in, const int* in_sizes, int n_in,
                              void* d_out, int out_size)
{
    const float* x  = (const float*)d_in[0];
    const float* W0 = (const float*)d_in[5];
    const float* W1 = (const float*)d_in[6];
    const float* b1 = (const float*)d_in[7];
    const float* W2 = (const float*)d_in[8];
    const float* b2 = (const float*)d_in[9];
    float* out = (float*)d_out;

    float *Wx, *g0, *sc, *pb, *n0, *n1, *n2, *g2;
    cudaGetSymbolAddress((void**)&Wx, d_Wx);
    cudaGetSymbolAddress((void**)&g0, d_g0);
    cudaGetSymbolAddress((void**)&sc, d_scores);
    cudaGetSymbolAddress((void**)&pb, d_pbuf);
    cudaGetSymbolAddress((void**)&n0, d_n0);
    cudaGetSymbolAddress((void**)&n1, d_n1);
    cudaGetSymbolAddress((void**)&n2, d_n2);
    cudaGetSymbolAddress((void**)&g2, d_g2);

    const int g1_smem_bytes = (BB * KC + 512 * 33) * (int)sizeof(float); // 97,920 B
    cudaFuncSetAttribute(g1_partial, cudaFuncAttributeMaxDynamicSharedMemorySize,
                         g1_smem_bytes);

    const float scale = 0.05773502691896258f;   // 1/sqrt(300)

    // Wx = x @ W0^T   (M=9600, N=300, K=300)
    gemm128<true><<<dim3(3, 75, 1), 256>>>(x, W0, Wx, BB * SS, EE, EE,
                                           EE, EE, EE, 0, 0, 0, 1.f);

    // ---- step 0 (all neurons zero): g0 = Wx, n1 = tanh(b1), n2 = tanh(b2) ----
    init_n12<<<33, 256>>>(b1, b2, n1, n2);
    gemm128<true><<<dim3(5, 5, BB), 256>>>(Wx, x, sc, SS, SS, EE,
                                           EE, EE, SS,
                                           (long)DD, (long)DD, (long)SS * SS, scale);
    softmax_rows<<<1200, 256>>>(sc);
    gemm128<false><<<dim3(3, 5, BB), 256>>>(sc, x, n0, SS, EE, SS,
                                            SS, EE, EE,
                                            (long)SS * SS, (long)DD, (long)DD, 1.f);

    // ---- steps 1..T-1 ----
    for (int t = 1; t < TT; t++) {
        g1_partial<<<KSPLIT, 256, g1_smem_bytes>>>(W1, n0, pb);        // old n0
        g0_kernel<<<704, 128>>>(W1, Wx, n1, g0);                       // old n1
        g2_kernel<<<1, 32>>>(n1, W2, b2, g2);                          // old n1
        g1_reduce<<<32, 256>>>(pb, b1, n2, W2, n1);                    // old n2 -> new n1
        n2_tanh<<<1, 32>>>(g2, n2);                                    // new n2
        gemm128<true><<<dim3(5, 5, BB), 256>>>(g0, x, sc, SS, SS, EE,
                                               EE, EE, SS,
                                               (long)DD, (long)DD, (long)SS * SS, scale);
        softmax_rows<<<1200, 256>>>(sc);
        gemm128<false><<<dim3(3, 5, BB), 256>>>(sc, x, n0, SS, EE, SS,
                                                SS, EE, EE,
                                                (long)SS * SS, (long)DD, (long)DD, 1.f);
    }

    final_copy<<<11283, 256>>>(n0, n1, n2, out);
}

// round 6
// speedup vs baseline: 1.8186x; 1.8186x over previous
#include <cuda_runtime.h>
#include <math.h>

// Problem constants
#define BB 16
#define SS 600
#define EE 300
#define HH 512
#define NCC 2
#define DD 180000          // S*E
#define TT 3
#define KSPLIT 375
#define KC 480             // KSPLIT*KC = DD, KC % 32 == 0

#define N0_ELEMS (BB*DD)        // 2,880,000
#define N1_ELEMS (BB*HH)        // 8,192
#define N2_ELEMS (BB*NCC)       // 32
#define SC_ELEMS (BB*SS*SS)     // 5,760,000

// -------- device scratch (no allocation allowed) --------
__device__ __align__(16) float d_Wx[N0_ELEMS];
__device__ __align__(16) float d_g0[N0_ELEMS];
__device__ __align__(16) float d_scores[SC_ELEMS];
__device__ __align__(16) float d_pbuf[KSPLIT * N1_ELEMS];
__device__ __align__(16) float d_n0[N0_ELEMS];
__device__ __align__(16) float d_n1[N1_ELEMS];
__device__ __align__(16) float d_n2[N2_ELEMS];
__device__ __align__(16) float d_g2[N2_ELEMS];

// ============================================================
// tf32 tensor-core GEMM (mma.sync.m16n8k8), fp32 accumulate.
// C[z] = alpha * A[z] * op(B[z])
//   NT=true : B stored [N,K]  (C[m,n] = sum_k A[m,k]*B[n,k])
//   NT=false: B stored [K,N]  (C[m,n] = sum_k A[m,k]*B[k,n])
// BM=BN=64, BK=32, 128 threads = 4 warps (2x2), warp tile 32x32.
// ============================================================
__device__ __forceinline__ unsigned f2tf(float f) {
    unsigned r;
    asm("cvt.rna.tf32.f32 %0, %1;" : "=r"(r) : "f"(f));
    return r;
}

__device__ __forceinline__ void mma_tf32(float* c, const unsigned* a, const unsigned* b) {
    asm volatile(
        "mma.sync.aligned.m16n8k8.row.col.f32.tf32.tf32.f32 "
        "{%0,%1,%2,%3}, {%4,%5,%6,%7}, {%8,%9}, {%0,%1,%2,%3};"
        : "+f"(c[0]), "+f"(c[1]), "+f"(c[2]), "+f"(c[3])
        : "r"(a[0]), "r"(a[1]), "r"(a[2]), "r"(a[3]),
          "r"(b[0]), "r"(b[1]));
}

template<bool NT>
__global__ __launch_bounds__(128)
void mma_gemm(const float* __restrict__ A, const float* __restrict__ Bm,
              float* __restrict__ C, int M, int N, int K,
              int lda, int ldb, int ldc,
              long sA, long sB, long sC, float alpha)
{
    // As: [64 m][36 k-pad]   (stride 36 -> frag reads conflict-free)
    // Bs NT: [64 n][36 k-pad]; Bs NN: [32 k][72 n-pad]
    __shared__ unsigned As[64 * 36];
    __shared__ unsigned Bs[2304];   // 64*36 == 32*72

    const float* Ab = A  + (long)blockIdx.z * sA;
    const float* Bb = Bm + (long)blockIdx.z * sB;
    float*       Cb = C  + (long)blockIdx.z * sC;

    const int m0 = blockIdx.y * 64;
    const int n0 = blockIdx.x * 64;
    const int tid = threadIdx.x;
    const int warp = tid >> 5;
    const int lane = tid & 31;
    const int wm = warp >> 1;       // 0..1
    const int wn = warp & 1;        // 0..1
    const int lr = lane >> 2;       // 0..7
    const int lc = lane & 3;        // 0..3

    float acc[2][4][4];
#pragma unroll
    for (int i = 0; i < 2; i++)
#pragma unroll
        for (int j = 0; j < 4; j++)
#pragma unroll
            for (int r = 0; r < 4; r++) acc[i][j][r] = 0.f;

    const float4 zero4 = make_float4(0.f, 0.f, 0.f, 0.f);

    for (int k0 = 0; k0 < K; k0 += 32) {
        __syncthreads();
        // ---- load A tile (64 x 32), tf32-convert, [m][k] stride 36 ----
#pragma unroll
        for (int i = 0; i < 4; i++) {
            int idx = i * 128 + tid;
            int row = idx >> 3;         // 0..63
            int q   = idx & 7;          // k quad
            int m = m0 + row, k = k0 + q * 4;
            float4 v = (m < M && k < K)
                ? *(const float4*)(Ab + (long)m * lda + k) : zero4;
            unsigned* s = &As[row * 36 + q * 4];
            s[0] = f2tf(v.x); s[1] = f2tf(v.y); s[2] = f2tf(v.z); s[3] = f2tf(v.w);
        }
        // ---- load B tile ----
        if (NT) {
#pragma unroll
            for (int i = 0; i < 4; i++) {
                int idx = i * 128 + tid;
                int row = idx >> 3;     // n 0..63
                int q   = idx & 7;
                int n = n0 + row, k = k0 + q * 4;
                float4 v = (n < N && k < K)
                    ? *(const float4*)(Bb + (long)n * ldb + k) : zero4;
                unsigned* s = &Bs[row * 36 + q * 4];
                s[0] = f2tf(v.x); s[1] = f2tf(v.y); s[2] = f2tf(v.z); s[3] = f2tf(v.w);
            }
        } else {
#pragma unroll
            for (int i = 0; i < 4; i++) {
                int idx = i * 128 + tid;
                int kr = idx >> 4;      // k 0..31
                int q  = idx & 15;      // n quad
                int k = k0 + kr, n = n0 + q * 4;
                float4 v = (k < K && n < N)
                    ? *(const float4*)(Bb + (long)k * ldb + n) : zero4;
                unsigned* s = &Bs[kr * 72 + q * 4];
                s[0] = f2tf(v.x); s[1] = f2tf(v.y); s[2] = f2tf(v.z); s[3] = f2tf(v.w);
            }
        }
        __syncthreads();

        // ---- compute: 4 k-steps of 8 ----
#pragma unroll
        for (int kk = 0; kk < 4; kk++) {
            int kb = kk * 8 + lc;
            unsigned a[2][4];
#pragma unroll
            for (int mt = 0; mt < 2; mt++) {
                int r = wm * 32 + mt * 16 + lr;
                a[mt][0] = As[r * 36 + kb];
                a[mt][1] = As[(r + 8) * 36 + kb];
                a[mt][2] = As[r * 36 + kb + 4];
                a[mt][3] = As[(r + 8) * 36 + kb + 4];
            }
            unsigned b[4][2];
#pragma unroll
            for (int nt = 0; nt < 4; nt++) {
                int n = wn * 32 + nt * 8 + lr;
                if (NT) {
                    b[nt][0] = Bs[n * 36 + kb];
                    b[nt][1] = Bs[n * 36 + kb + 4];
                } else {
                    b[nt][0] = Bs[kb * 72 + n];
                    b[nt][1] = Bs[(kb + 4) * 72 + n];
                }
            }
#pragma unroll
            for (int mt = 0; mt < 2; mt++)
#pragma unroll
                for (int nt = 0; nt < 4; nt++)
                    mma_tf32(acc[mt][nt], a[mt], b[nt]);
        }
    }

    // ---- epilogue ----
#pragma unroll
    for (int mt = 0; mt < 2; mt++) {
#pragma unroll
        for (int nt = 0; nt < 4; nt++) {
            int row = m0 + wm * 32 + mt * 16 + lr;
            int col = n0 + wn * 32 + nt * 8 + lc * 2;
            float* cc = acc[mt][nt];
            if (row < M) {
                if (col < N)     Cb[(long)row * ldc + col]     = alpha * cc[0];
                if (col + 1 < N) Cb[(long)row * ldc + col + 1] = alpha * cc[1];
            }
            if (row + 8 < M) {
                if (col < N)     Cb[(long)(row + 8) * ldc + col]     = alpha * cc[2];
                if (col + 1 < N) Cb[(long)(row + 8) * ldc + col + 1] = alpha * cc[3];
            }
        }
    }
}

// ============================================================
// g0[b,d] = Wx[b,d] + sum_h n1[b,h] * W1[h,d]
// ============================================================
__global__ __launch_bounds__(128)
void g0_kernel(const float* __restrict__ W1, const float* __restrict__ Wx,
               const float* __restrict__ n1, float* __restrict__ g0)
{
    __shared__ float sn1[HH * BB];   // [h][b], 32 KB
    const int tid = threadIdx.x;
    for (int i = tid; i < BB * HH; i += 128) {
        int b = i >> 9, h = i & 511;
        sn1[h * BB + b] = n1[i];
    }
    __syncthreads();

    long d0 = (long)blockIdx.x * 256 + tid * 2;
    if (d0 >= DD) return;

    float acc0[BB], acc1[BB];
#pragma unroll
    for (int b = 0; b < BB; b++) {
        acc0[b] = Wx[(long)b * DD + d0];
        acc1[b] = Wx[(long)b * DD + d0 + 1];
    }
    const float* wp = W1 + d0;
    for (int h = 0; h < HH; h++) {
        float2 w = *(const float2*)wp; wp += DD;
        const float* s = &sn1[h * BB];
#pragma unroll
        for (int b = 0; b < BB; b++) {
            float nv = s[b];
            acc0[b] += nv * w.x;
            acc1[b] += nv * w.y;
        }
    }
#pragma unroll
    for (int b = 0; b < BB; b++) {
        g0[(long)b * DD + d0]     = acc0[b];
        g0[(long)b * DD + d0 + 1] = acc1[b];
    }
}

// ============================================================
// g1 split-K partial: pbuf[blk][b][h] = sum_{d in chunk} n0[b,d]*W1[h,d]
// ============================================================
extern __shared__ float g1_smem[];
__global__ __launch_bounds__(256)
void g1_partial(const float* __restrict__ W1, const float* __restrict__ n0,
                float* __restrict__ pbuf)
{
    float* sn0 = g1_smem;               // 16*KC
    float* sW1 = g1_smem + BB * KC;     // 512*33

    const int tid = threadIdx.x;
    const long kb = (long)blockIdx.x * KC;

    for (int i = tid; i < BB * KC; i += 256) {
        int b = i / KC, k = i - b * KC;
        sn0[i] = n0[(long)b * DD + kb + k];
    }

    float acc0[BB], acc1[BB];
#pragma unroll
    for (int b = 0; b < BB; b++) { acc0[b] = 0.f; acc1[b] = 0.f; }

    for (int sub = 0; sub < KC / 32; sub++) {
        __syncthreads();
#pragma unroll
        for (int i = 0; i < 16; i++) {
            int idx = i * 256 + tid;
            int row = idx >> 3, q = idx & 7;
            float4 v = *(const float4*)(W1 + (long)row * DD + kb + sub * 32 + q * 4);
            float* s = &sW1[row * 33 + q * 4];
            s[0] = v.x; s[1] = v.y; s[2] = v.z; s[3] = v.w;
        }
        __syncthreads();

#pragma unroll 4
        for (int kk = 0; kk < 32; kk++) {
            float w0 = sW1[tid * 33 + kk];
            float w1 = sW1[(tid + 256) * 33 + kk];
            const float* s = &sn0[sub * 32 + kk];
#pragma unroll
            for (int b = 0; b < BB; b++) {
                float nv = s[b * KC];
                acc0[b] += w0 * nv;
                acc1[b] += w1 * nv;
            }
        }
    }

    long base = (long)blockIdx.x * N1_ELEMS;
#pragma unroll
    for (int b = 0; b < BB; b++) {
        pbuf[base + b * HH + tid]       = acc0[b];
        pbuf[base + b * HH + tid + 256] = acc1[b];
    }
}

// g1 reduce + bias + n2@W2 + tanh -> n1
__global__ void g1_reduce(const float* __restrict__ pbuf, const float* __restrict__ b1,
                          const float* __restrict__ n2, const float* __restrict__ W2,
                          float* __restrict__ n1)
{
    int idx = blockIdx.x * blockDim.x + threadIdx.x;   // 8192
    int b = idx >> 9, h = idx & 511;
    float s = b1[h] + n2[b * 2] * W2[h] + n2[b * 2 + 1] * W2[HH + h];
    for (int k = 0; k < KSPLIT; k++)
        s += pbuf[(long)k * N1_ELEMS + idx];
    n1[idx] = tanhf(s);
}

// g2[b,c] = b2[c] + sum_h n1[b,h]*W2[c,h]
__global__ void g2_kernel(const float* __restrict__ n1, const float* __restrict__ W2,
                          const float* __restrict__ b2, float* __restrict__ g2)
{
    int t = threadIdx.x;
    if (t < 32) {
        int b = t >> 1, c = t & 1;
        float s = 0.f;
        for (int h = 0; h < HH; h++)
            s += n1[b * HH + h] * W2[c * HH + h];
        g2[t] = b2[c] + s;
    }
}

__global__ void n2_tanh(const float* __restrict__ g2, float* __restrict__ n2)
{
    int t = threadIdx.x;
    if (t < 32) n2[t] = tanhf(g2[t]);
}

// step-0 closed form: n1 = tanh(b1), n2 = tanh(b2)
__global__ void init_n12(const float* __restrict__ b1, const float* __restrict__ b2,
                         float* __restrict__ n1, float* __restrict__ n2)
{
    int idx = blockIdx.x * blockDim.x + threadIdx.x;
    if (idx < N1_ELEMS) n1[idx] = tanhf(b1[idx & 511]);
    else if (idx < N1_ELEMS + N2_ELEMS) {
        int r = idx - N1_ELEMS;
        n2[r] = tanhf(b2[r & 1]);
    }
}

// row softmax over 16*600 rows of length 600; one warp per row
__global__ void softmax_rows(float* __restrict__ S)
{
    int gwarp = (blockIdx.x * blockDim.x + threadIdx.x) >> 5;
    int lane = threadIdx.x & 31;
    if (gwarp >= BB * SS) return;
    float* row = S + (long)gwarp * SS;

    float v[19];
    float mx = -INFINITY;
#pragma unroll
    for (int i = 0; i < 19; i++) {
        int c = lane + i * 32;
        v[i] = (c < SS) ? row[c] : -INFINITY;
        mx = fmaxf(mx, v[i]);
    }
#pragma unroll
    for (int o = 16; o; o >>= 1) mx = fmaxf(mx, __shfl_xor_sync(0xffffffffu, mx, o));

    float sum = 0.f;
#pragma unroll
    for (int i = 0; i < 19; i++) {
        v[i] = expf(v[i] - mx);
        sum += v[i];
    }
#pragma unroll
    for (int o = 16; o; o >>= 1) sum += __shfl_xor_sync(0xffffffffu, sum, o);
    float inv = 1.f / sum;
#pragma unroll
    for (int i = 0; i < 19; i++) {
        int c = lane + i * 32;
        if (c < SS) row[c] = v[i] * inv;
    }
}

// concat (n0, n1, n2) into d_out
__global__ void final_copy(const float* __restrict__ n0, const float* __restrict__ n1,
                           const float* __restrict__ n2, float* __restrict__ out)
{
    int idx = blockIdx.x * blockDim.x + threadIdx.x;
    if (idx < N0_ELEMS) out[idx] = n0[idx];
    else if (idx < N0_ELEMS + N1_ELEMS) out[idx] = n1[idx - N0_ELEMS];
    else if (idx < N0_ELEMS + N1_ELEMS + N2_ELEMS) out[idx] = n2[idx - N0_ELEMS - N1_ELEMS];
}

// ============================================================
extern "C" void kernel_launch(void* const* d_in, const int* in_sizes, int n_in,
                              void* d_out, int out_size)
{
    const float* x  = (const float*)d_in[0];
    const float* W0 = (const float*)d_in[5];
    const float* W1 = (const float*)d_in[6];
    const float* b1 = (const float*)d_in[7];
    const float* W2 = (const float*)d_in[8];
    const float* b2 = (const float*)d_in[9];
    float* out = (float*)d_out;

    float *Wx, *g0, *sc, *pb, *n0, *n1, *n2, *g2;
    cudaGetSymbolAddress((void**)&Wx, d_Wx);
    cudaGetSymbolAddress((void**)&g0, d_g0);
    cudaGetSymbolAddress((void**)&sc, d_scores);
    cudaGetSymbolAddress((void**)&pb, d_pbuf);
    cudaGetSymbolAddress((void**)&n0, d_n0);
    cudaGetSymbolAddress((void**)&n1, d_n1);
    cudaGetSymbolAddress((void**)&n2, d_n2);
    cudaGetSymbolAddress((void**)&g2, d_g2);

    const int g1_smem_bytes = (BB * KC + 512 * 33) * (int)sizeof(float); // 97,920 B
    cudaFuncSetAttribute(g1_partial, cudaFuncAttributeMaxDynamicSharedMemorySize,
                         g1_smem_bytes);

    const float scale = 0.05773502691896258f;   // 1/sqrt(300)

    // Wx = x @ W0^T   (NT: M=9600, N=300, K=300)
    mma_gemm<true><<<dim3(5, 150, 1), 128>>>(x, W0, Wx, BB * SS, EE, EE,
                                             EE, EE, EE, 0, 0, 0, 1.f);

    // ---- step 0 (all neurons zero): g0 = Wx, n1 = tanh(b1), n2 = tanh(b2) ----
    init_n12<<<33, 256>>>(b1, b2, n1, n2);
    mma_gemm<true><<<dim3(10, 10, BB), 128>>>(Wx, x, sc, SS, SS, EE,
                                              EE, EE, SS,
                                              (long)DD, (long)DD, (long)SS * SS, scale);
    softmax_rows<<<1200, 256>>>(sc);
    mma_gemm<false><<<dim3(5, 10, BB), 128>>>(sc, x, n0, SS, EE, SS,
                                              SS, EE, EE,
                                              (long)SS * SS, (long)DD, (long)DD, 1.f);

    // ---- steps 1..T-1 ----
    for (int t = 1; t < TT; t++) {
        g1_partial<<<KSPLIT, 256, g1_smem_bytes>>>(W1, n0, pb);        // old n0
        g0_kernel<<<704, 128>>>(W1, Wx, n1, g0);                       // old n1
        g2_kernel<<<1, 32>>>(n1, W2, b2, g2);                          // old n1
        g1_reduce<<<32, 256>>>(pb, b1, n2, W2, n1);                    // old n2 -> new n1
        n2_tanh<<<1, 32>>>(g2, n2);                                    // new n2
        mma_gemm<true><<<dim3(10, 10, BB), 128>>>(g0, x, sc, SS, SS, EE,
                                                  EE, EE, SS,
                                                  (long)DD, (long)DD, (long)SS * SS, scale);
        softmax_rows<<<1200, 256>>>(sc);
        mma_gemm<false><<<dim3(5, 10, BB), 128>>>(sc, x, n0, SS, EE, SS,
                                                  SS, EE, EE,
                                                  (long)SS * SS, (long)DD, (long)DD, 1.f);
    }

    final_copy<<<11283, 256>>>(n0, n1, n2, out);
}

// round 10
// speedup vs baseline: 2.2692x; 1.2477x over previous
#include <cuda_runtime.h>
#include <math.h>

// Problem constants
#define BB 16
#define SS 600
#define EE 300
#define HH 512
#define NCC 2
#define DD 180000          // S*E
#define TT 3

#define CD 256             // d-chunk per fused block
#define NBLK 704           // ceil(DD/CD)
#define W1_PITCH 260       // 256+4 pad (pitch mod 32 == 4 -> conflict-free frags)
#define N1_PITCH 516       // 512+4
#define TILE_ELEMS (64*W1_PITCH)

#define N0_ELEMS (BB*DD)        // 2,880,000
#define N1_ELEMS (BB*HH)        // 8,192
#define N2_ELEMS (BB*NCC)       // 32
#define SC_ELEMS (BB*SS*SS)     // 5,760,000

// -------- device scratch (no allocation allowed) --------
__device__ __align__(16) float d_Wx[N0_ELEMS];
__device__ __align__(16) float d_g0[N0_ELEMS];
__device__ __align__(16) float d_scores[SC_ELEMS];
__device__ __align__(16) float d_pbuf[NBLK * N1_ELEMS];   // 23 MB
__device__ __align__(16) float d_n0[N0_ELEMS];
__device__ __align__(16) float d_n1[N1_ELEMS];
__device__ __align__(16) float d_n2[N2_ELEMS];
__device__ __align__(16) float d_g2[N2_ELEMS];

// ============================================================
// tf32 helpers
// ============================================================
__device__ __forceinline__ unsigned f2tf(float f) {
    unsigned r;
    asm("cvt.rna.tf32.f32 %0, %1;" : "=r"(r) : "f"(f));
    return r;
}

__device__ __forceinline__ void mma_tf32(float* c, const unsigned* a, const unsigned* b) {
    asm volatile(
        "mma.sync.aligned.m16n8k8.row.col.f32.tf32.tf32.f32 "
        "{%0,%1,%2,%3}, {%4,%5,%6,%7}, {%8,%9}, {%0,%1,%2,%3};"
        : "+f"(c[0]), "+f"(c[1]), "+f"(c[2]), "+f"(c[3])
        : "r"(a[0]), "r"(a[1]), "r"(a[2]), "r"(a[3]),
          "r"(b[0]), "r"(b[1]));
}

// ============================================================
// Generic tf32 tensor-core GEMM (unchanged from R3, validated)
// ============================================================
template<bool NT>
__global__ __launch_bounds__(128)
void mma_gemm(const float* __restrict__ A, const float* __restrict__ Bm,
              float* __restrict__ C, int M, int N, int K,
              int lda, int ldb, int ldc,
              long sA, long sB, long sC, float alpha)
{
    __shared__ unsigned As[64 * 36];
    __shared__ unsigned Bs[2304];   // 64*36 == 32*72

    const float* Ab = A  + (long)blockIdx.z * sA;
    const float* Bb = Bm + (long)blockIdx.z * sB;
    float*       Cb = C  + (long)blockIdx.z * sC;

    const int m0 = blockIdx.y * 64;
    const int n0 = blockIdx.x * 64;
    const int tid = threadIdx.x;
    const int warp = tid >> 5;
    const int lane = tid & 31;
    const int wm = warp >> 1;
    const int wn = warp & 1;
    const int lr = lane >> 2;
    const int lc = lane & 3;

    float acc[2][4][4];
#pragma unroll
    for (int i = 0; i < 2; i++)
#pragma unroll
        for (int j = 0; j < 4; j++)
#pragma unroll
            for (int r = 0; r < 4; r++) acc[i][j][r] = 0.f;

    const float4 zero4 = make_float4(0.f, 0.f, 0.f, 0.f);

    for (int k0 = 0; k0 < K; k0 += 32) {
        __syncthreads();
#pragma unroll
        for (int i = 0; i < 4; i++) {
            int idx = i * 128 + tid;
            int row = idx >> 3;
            int q   = idx & 7;
            int m = m0 + row, k = k0 + q * 4;
            float4 v = (m < M && k < K)
                ? *(const float4*)(Ab + (long)m * lda + k) : zero4;
            unsigned* s = &As[row * 36 + q * 4];
            s[0] = f2tf(v.x); s[1] = f2tf(v.y); s[2] = f2tf(v.z); s[3] = f2tf(v.w);
        }
        if (NT) {
#pragma unroll
            for (int i = 0; i < 4; i++) {
                int idx = i * 128 + tid;
                int row = idx >> 3;
                int q   = idx & 7;
                int n = n0 + row, k = k0 + q * 4;
                float4 v = (n < N && k < K)
                    ? *(const float4*)(Bb + (long)n * ldb + k) : zero4;
                unsigned* s = &Bs[row * 36 + q * 4];
                s[0] = f2tf(v.x); s[1] = f2tf(v.y); s[2] = f2tf(v.z); s[3] = f2tf(v.w);
            }
        } else {
#pragma unroll
            for (int i = 0; i < 4; i++) {
                int idx = i * 128 + tid;
                int kr = idx >> 4;
                int q  = idx & 15;
                int k = k0 + kr, n = n0 + q * 4;
                float4 v = (k < K && n < N)
                    ? *(const float4*)(Bb + (long)k * ldb + n) : zero4;
                unsigned* s = &Bs[kr * 72 + q * 4];
                s[0] = f2tf(v.x); s[1] = f2tf(v.y); s[2] = f2tf(v.z); s[3] = f2tf(v.w);
            }
        }
        __syncthreads();

#pragma unroll
        for (int kk = 0; kk < 4; kk++) {
            int kb = kk * 8 + lc;
            unsigned a[2][4];
#pragma unroll
            for (int mt = 0; mt < 2; mt++) {
                int r = wm * 32 + mt * 16 + lr;
                a[mt][0] = As[r * 36 + kb];
                a[mt][1] = As[(r + 8) * 36 + kb];
                a[mt][2] = As[r * 36 + kb + 4];
                a[mt][3] = As[(r + 8) * 36 + kb + 4];
            }
            unsigned b[4][2];
#pragma unroll
            for (int nt = 0; nt < 4; nt++) {
                int n = wn * 32 + nt * 8 + lr;
                if (NT) {
                    b[nt][0] = Bs[n * 36 + kb];
                    b[nt][1] = Bs[n * 36 + kb + 4];
                } else {
                    b[nt][0] = Bs[kb * 72 + n];
                    b[nt][1] = Bs[(kb + 4) * 72 + n];
                }
            }
#pragma unroll
            for (int mt = 0; mt < 2; mt++)
#pragma unroll
                for (int nt = 0; nt < 4; nt++)
                    mma_tf32(acc[mt][nt], a[mt], b[nt]);
        }
    }

#pragma unroll
    for (int mt = 0; mt < 2; mt++) {
#pragma unroll
        for (int nt = 0; nt < 4; nt++) {
            int row = m0 + wm * 32 + mt * 16 + lr;
            int col = n0 + wn * 32 + nt * 8 + lc * 2;
            float* cc = acc[mt][nt];
            if (row < M) {
                if (col < N)     Cb[(long)row * ldc + col]     = alpha * cc[0];
                if (col + 1 < N) Cb[(long)row * ldc + col + 1] = alpha * cc[1];
            }
            if (row + 8 < M) {
                if (col < N)     Cb[(long)(row + 8) * ldc + col]     = alpha * cc[2];
                if (col + 1 < N) Cb[(long)(row + 8) * ldc + col + 1] = alpha * cc[3];
            }
        }
    }
}

// ============================================================
// Fused W1 kernel: ONE pass over W1 computes BOTH
//   g0[b, dchunk] = Wx + n1 @ W1[:, dchunk]         (K = 512 h)
//   pbuf[blk][b][h] = n0[b, dchunk] @ W1[:, dchunk]^T (K = d-chunk)
// 256 threads = 8 warps; 8 h-tiles of 64; cp.async double-buffered.
// ============================================================
__device__ __forceinline__ void issue_w1_tile(
    const float* __restrict__ W1, unsigned* dstbase, long d0, int ht, int tid)
{
#pragma unroll
    for (int p = 0; p < 16; p++) {
        int j = p * 256 + tid;
        int row = j >> 6;         // 0..63
        int c4  = j & 63;         // float4 col
        bool valid = (d0 + c4 * 4 + 4) <= DD;
        const float* src = valid ? (W1 + (long)(ht * 64 + row) * DD + d0 + c4 * 4)
                                 : W1;
        unsigned dst = (unsigned)__cvta_generic_to_shared(dstbase + row * W1_PITCH + c4 * 4);
        int sz = valid ? 16 : 0;
        asm volatile("cp.async.cg.shared.global [%0], [%1], 16, %2;\n"
                     :: "r"(dst), "l"(src), "r"(sz));
    }
    asm volatile("cp.async.commit_group;\n" ::: "memory");
}

extern __shared__ unsigned fw_smem[];
__global__ __launch_bounds__(256)
void fused_w1(const float* __restrict__ W1, const float* __restrict__ Wx,
              const float* __restrict__ n0, const float* __restrict__ n1,
              float* __restrict__ g0, float* __restrict__ pbuf)
{
    unsigned* sW1 = fw_smem;                       // 2 * TILE_ELEMS (raw fp32 bits)
    unsigned* sn1 = fw_smem + 2 * TILE_ELEMS;      // 16 * 516 (tf32)
    unsigned* sn0 = sn1 + 16 * N1_PITCH;           // 16 * 260 (tf32)

    const int tid = threadIdx.x;
    const int warp = tid >> 5, lane = tid & 31;
    const int lr = lane >> 2, lc = lane & 3;
    const long d0 = (long)blockIdx.x * CD;

    // stage n1 (16x512) and n0 chunk (16x256), rna-converted
    for (int i = tid; i < BB * HH; i += 256) {
        int b = i >> 9, h = i & 511;
        sn1[b * N1_PITCH + h] = f2tf(n1[i]);
    }
    for (int i = tid; i < BB * CD; i += 256) {
        int b = i >> 8, d = i & (CD - 1);
        float v = (d0 + d < DD) ? n0[(long)b * DD + d0 + d] : 0.f;
        sn0[b * W1_PITCH + d] = f2tf(v);
    }

    issue_w1_tile(W1, sW1, d0, 0, tid);

    float accg0[4][4];
#pragma unroll
    for (int i = 0; i < 4; i++)
#pragma unroll
        for (int j = 0; j < 4; j++) accg0[i][j] = 0.f;

    for (int ht = 0; ht < 8; ht++) {
        asm volatile("cp.async.wait_group 0;\n" ::: "memory");
        __syncthreads();
        if (ht < 7)
            issue_w1_tile(W1, sW1 + ((ht + 1) & 1) * TILE_ELEMS, d0, ht + 1, tid);
        const unsigned* tw = sW1 + (ht & 1) * TILE_ELEMS;

        // ---- g0: C[b, d] += n1[b, htile] * W1[htile, d] ----
#pragma unroll
        for (int ks = 0; ks < 8; ks++) {
            int kg = ht * 64 + ks * 8 + lc;
            unsigned a[4];
            a[0] = sn1[lr * N1_PITCH + kg];
            a[1] = sn1[(lr + 8) * N1_PITCH + kg];
            a[2] = sn1[lr * N1_PITCH + kg + 4];
            a[3] = sn1[(lr + 8) * N1_PITCH + kg + 4];
#pragma unroll
            for (int nt = 0; nt < 4; nt++) {
                int n = warp * 32 + nt * 8 + lr;
                unsigned b[2];
                b[0] = tw[(ks * 8 + lc) * W1_PITCH + n];
                b[1] = tw[(ks * 8 + lc + 4) * W1_PITCH + n];
                mma_tf32(accg0[nt], a, b);
            }
        }

        // ---- g1 partial: C[b, h(tile)] = n0[b, dchunk] * W1[h, dchunk] ----
        float accg1[4] = {0.f, 0.f, 0.f, 0.f};
#pragma unroll
        for (int ks = 0; ks < 32; ks++) {
            int kb = ks * 8 + lc;
            unsigned a[4];
            a[0] = sn0[lr * W1_PITCH + kb];
            a[1] = sn0[(lr + 8) * W1_PITCH + kb];
            a[2] = sn0[lr * W1_PITCH + kb + 4];
            a[3] = sn0[(lr + 8) * W1_PITCH + kb + 4];
            unsigned b[2];
            b[0] = tw[(warp * 8 + lr) * W1_PITCH + kb];
            b[1] = tw[(warp * 8 + lr) * W1_PITCH + kb + 4];
            mma_tf32(accg1, a, b);
        }
        {
            int hg = ht * 64 + warp * 8 + lc * 2;
            long pb = (long)blockIdx.x * N1_ELEMS;
            pbuf[pb + lr * HH + hg]           = accg1[0];
            pbuf[pb + lr * HH + hg + 1]       = accg1[1];
            pbuf[pb + (lr + 8) * HH + hg]     = accg1[2];
            pbuf[pb + (lr + 8) * HH + hg + 1] = accg1[3];
        }
    }

    // ---- g0 epilogue: add Wx, store ----
#pragma unroll
    for (int nt = 0; nt < 4; nt++) {
        long dg = d0 + warp * 32 + nt * 8 + lc * 2;
        if (dg < DD) {
            g0[(long)lr * DD + dg]       = Wx[(long)lr * DD + dg]       + accg0[nt][0];
            g0[(long)(lr + 8) * DD + dg] = Wx[(long)(lr + 8) * DD + dg] + accg0[nt][2];
            if (dg + 1 < DD) {
                g0[(long)lr * DD + dg + 1]       = Wx[(long)lr * DD + dg + 1]       + accg0[nt][1];
                g0[(long)(lr + 8) * DD + dg + 1] = Wx[(long)(lr + 8) * DD + dg + 1] + accg0[nt][3];
            }
        }
    }
}

// g1 reduce + bias + n2@W2 + tanh -> n1
__global__ void g1_reduce(const float* __restrict__ pbuf, const float* __restrict__ b1,
                          const float* __restrict__ n2, const float* __restrict__ W2,
                          float* __restrict__ n1)
{
    int idx = blockIdx.x * blockDim.x + threadIdx.x;   // 8192
    int b = idx >> 9, h = idx & 511;
    float s = b1[h] + n2[b * 2] * W2[h] + n2[b * 2 + 1] * W2[HH + h];
    for (int k = 0; k < NBLK; k++)
        s += pbuf[(long)k * N1_ELEMS + idx];
    n1[idx] = tanhf(s);
}

// g2[b,c] = b2[c] + sum_h n1[b,h]*W2[c,h]
__global__ void g2_kernel(const float* __restrict__ n1, const float* __restrict__ W2,
                          const float* __restrict__ b2, float* __restrict__ g2)
{
    int t = threadIdx.x;
    if (t < 32) {
        int b = t >> 1, c = t & 1;
        float s = 0.f;
        for (int h = 0; h < HH; h++)
            s += n1[b * HH + h] * W2[c * HH + h];
        g2[t] = b2[c] + s;
    }
}

__global__ void n2_tanh(const float* __restrict__ g2, float* __restrict__ n2)
{
    int t = threadIdx.x;
    if (t < 32) n2[t] = tanhf(g2[t]);
}

// step-0 closed form: n1 = tanh(b1), n2 = tanh(b2)
__global__ void init_n12(const float* __restrict__ b1, const float* __restrict__ b2,
                         float* __restrict__ n1, float* __restrict__ n2)
{
    int idx = blockIdx.x * blockDim.x + threadIdx.x;
    if (idx < N1_ELEMS) n1[idx] = tanhf(b1[idx & 511]);
    else if (idx < N1_ELEMS + N2_ELEMS) {
        int r = idx - N1_ELEMS;
        n2[r] = tanhf(b2[r & 1]);
    }
}

// row softmax over 16*600 rows of length 600; one warp per row
__global__ void softmax_rows(float* __restrict__ S)
{
    int gwarp = (blockIdx.x * blockDim.x + threadIdx.x) >> 5;
    int lane = threadIdx.x & 31;
    if (gwarp >= BB * SS) return;
    float* row = S + (long)gwarp * SS;

    float v[19];
    float mx = -INFINITY;
#pragma unroll
    for (int i = 0; i < 19; i++) {
        int c = lane + i * 32;
        v[i] = (c < SS) ? row[c] : -INFINITY;
        mx = fmaxf(mx, v[i]);
    }
#pragma unroll
    for (int o = 16; o; o >>= 1) mx = fmaxf(mx, __shfl_xor_sync(0xffffffffu, mx, o));

    float sum = 0.f;
#pragma unroll
    for (int i = 0; i < 19; i++) {
        v[i] = expf(v[i] - mx);
        sum += v[i];
    }
#pragma unroll
    for (int o = 16; o; o >>= 1) sum += __shfl_xor_sync(0xffffffffu, sum, o);
    float inv = 1.f / sum;
#pragma unroll
    for (int i = 0; i < 19; i++) {
        int c = lane + i * 32;
        if (c < SS) row[c] = v[i] * inv;
    }
}

// copy n1, n2 tails into out (n0 written directly by last GEMM)
__global__ void tail_copy(const float* __restrict__ n1, const float* __restrict__ n2,
                          float* __restrict__ out)
{
    int idx = blockIdx.x * blockDim.x + threadIdx.x;
    if (idx < N1_ELEMS) out[N0_ELEMS + idx] = n1[idx];
    else if (idx < N1_ELEMS + N2_ELEMS) out[N0_ELEMS + idx] = n2[idx - N1_ELEMS];
}

// ============================================================
extern "C" void kernel_launch(void* const* d_in, const int* in_sizes, int n_in,
                              void* d_out, int out_size)
{
    const float* x  = (const float*)d_in[0];
    const float* W0 = (const float*)d_in[5];
    const float* W1 = (const float*)d_in[6];
    const float* b1 = (const float*)d_in[7];
    const float* W2 = (const float*)d_in[8];
    const float* b2 = (const float*)d_in[9];
    float* out = (float*)d_out;

    float *Wx, *g0, *sc, *pb, *n0, *n1, *n2, *g2;
    cudaGetSymbolAddress((void**)&Wx, d_Wx);
    cudaGetSymbolAddress((void**)&g0, d_g0);
    cudaGetSymbolAddress((void**)&sc, d_scores);
    cudaGetSymbolAddress((void**)&pb, d_pbuf);
    cudaGetSymbolAddress((void**)&n0, d_n0);
    cudaGetSymbolAddress((void**)&n1, d_n1);
    cudaGetSymbolAddress((void**)&n2, d_n2);
    cudaGetSymbolAddress((void**)&g2, d_g2);

    const int fw_smem_bytes = (2 * TILE_ELEMS + 16 * N1_PITCH + 16 * W1_PITCH)
                              * (int)sizeof(unsigned);   // 182,784 B
    static int attr_done = 0;
    cudaFuncSetAttribute(fused_w1, cudaFuncAttributeMaxDynamicSharedMemorySize,
                         fw_smem_bytes);
    (void)attr_done;

    const float scale = 0.05773502691896258f;   // 1/sqrt(300)

    // Wx = x @ W0^T   (NT: M=9600, N=300, K=300)
    mma_gemm<true><<<dim3(5, 150, 1), 128>>>(x, W0, Wx, BB * SS, EE, EE,
                                             EE, EE, EE, 0, 0, 0, 1.f);

    // ---- step 0 (all neurons zero): g0 = Wx, n1 = tanh(b1), n2 = tanh(b2) ----
    init_n12<<<33, 256>>>(b1, b2, n1, n2);
    mma_gemm<true><<<dim3(10, 10, BB), 128>>>(Wx, x, sc, SS, SS, EE,
                                              EE, EE, SS,
                                              (long)DD, (long)DD, (long)SS * SS, scale);
    softmax_rows<<<1200, 256>>>(sc);
    mma_gemm<false><<<dim3(5, 10, BB), 128>>>(sc, x, n0, SS, EE, SS,
                                              SS, EE, EE,
                                              (long)SS * SS, (long)DD, (long)DD, 1.f);

    // ---- steps 1..T-1 ----
    for (int t = 1; t < TT; t++) {
        // one W1 pass computes g0 (old n1) and g1 partials (old n0)
        fused_w1<<<NBLK, 256, fw_smem_bytes>>>(W1, Wx, n0, n1, g0, pb);
        g2_kernel<<<1, 32>>>(n1, W2, b2, g2);                          // old n1
        g1_reduce<<<32, 256>>>(pb, b1, n2, W2, n1);                    // old n2 -> new n1
        n2_tanh<<<1, 32>>>(g2, n2);                                    // new n2
        mma_gemm<true><<<dim3(10, 10, BB), 128>>>(g0, x, sc, SS, SS, EE,
                                                  EE, EE, SS,
                                                  (long)DD, (long)DD, (long)SS * SS, scale);
        softmax_rows<<<1200, 256>>>(sc);
        float* n0dst = (t == TT - 1) ? out : n0;    // last step writes output directly
        mma_gemm<false><<<dim3(5, 10, BB), 128>>>(sc, x, n0dst, SS, EE, SS,
                                                  SS, EE, EE,
                                                  (long)SS * SS, (long)DD, (long)DD, 1.f);
    }

    tail_copy<<<33, 256>>>(n1, n2, out);
}